// round 7
// baseline (speedup 1.0000x reference)
#include <cuda_runtime.h>
#include <cstdint>

// SharedRadialLinearTransform: out[n,s,a,m] = sum_r x[n,r,a,m] * W[group(a),r,s]
// x: [2048, 12, 20, 128] f32 (252 MB) contiguous per node (120 KB slabs).
// R7 (= R6 resubmit, host-side rule fix): persistent block per SM;
// cp.async.bulk streams contiguous 60 KB half-node slabs through a 3-stage
// smem ring -> 148 long sequential DRAM read streams instead of ~3500
// interleaved 512B streams. Accumulators live in regs across the two halves
// of a node; stores overlap the next bulk load.

constexpr int RAD = 12;
constexpr int ANG = 20;
constexpr int EMB = 128;
constexpr int NG  = 4;
constexpr int HALF_R = 6;
constexpr int THREADS = 640;                       // 20 a * 32 m4 cells
constexpr int TILE_F4 = HALF_R * ANG * (EMB / 4);  // 3840 float4 = 61440 B
constexpr int TILE_BYTES = TILE_F4 * 16;
constexpr int STAGES = 3;                          // 184320 B dynamic smem
constexpr int NODE_FLOATS = RAD * ANG * EMB;       // 30720
constexpr int HALF_BYTES = TILE_BYTES;             // 61440

__device__ __forceinline__ uint32_t smem_u32(const void* p) {
    uint32_t a;
    asm("{ .reg .u64 t; cvta.to.shared.u64 t, %1; cvt.u32.u64 %0, t; }"
        : "=r"(a) : "l"(p));
    return a;
}

__device__ __forceinline__ void mbar_init(uint32_t mbar, uint32_t count) {
    asm volatile("mbarrier.init.shared.b64 [%0], %1;" :: "r"(mbar), "r"(count) : "memory");
}

__device__ __forceinline__ void bulk_load(uint32_t dst, const char* src,
                                          uint32_t bytes, uint32_t mbar) {
    asm volatile("mbarrier.arrive.expect_tx.shared.b64 _, [%0], %1;"
                 :: "r"(mbar), "r"(bytes) : "memory");
    asm volatile("cp.async.bulk.shared::cta.global.mbarrier::complete_tx::bytes "
                 "[%0], [%1], %2, [%3];"
                 :: "r"(dst), "l"(src), "r"(bytes), "r"(mbar) : "memory");
}

__device__ __forceinline__ void mbar_wait(uint32_t mbar, uint32_t parity) {
    uint32_t done;
    asm volatile(
        "{\n\t.reg .pred p;\n\t"
        "mbarrier.try_wait.parity.acquire.cta.shared::cta.b64 p, [%1], %2;\n\t"
        "selp.b32 %0, 1, 0, p;\n\t}"
        : "=r"(done) : "r"(mbar), "r"(parity) : "memory");
    if (!done) {
        asm volatile(
            "{\n\t.reg .pred P1;\n\t"
            "WAIT_LOOP_%=:\n\t"
            "mbarrier.try_wait.parity.acquire.cta.shared::cta.b64 P1, [%0], %1, 0x989680;\n\t"
            "@P1 bra.uni WAIT_DONE_%=;\n\t"
            "bra.uni WAIT_LOOP_%=;\n\t"
            "WAIT_DONE_%=:\n\t}"
            :: "r"(mbar), "r"(parity) : "memory");
    }
}

__global__ __launch_bounds__(THREADS, 1)
void srlt_kernel(const float* __restrict__ x,
                 const float*  __restrict__ W,
                 float4* __restrict__ out,
                 int n_nodes)
{
    extern __shared__ float4 stage[];            // STAGES * TILE_F4 float4
    __shared__ float w[NG * RAD * RAD];          // 576 floats
    __shared__ __align__(8) uint64_t full_mbar[STAGES];

    const int tid = threadIdx.x;

    for (int i = tid; i < NG * RAD * RAD; i += THREADS)
        w[i] = W[i];

    uint32_t mbar_base = smem_u32(full_mbar);
    if (tid == 0) {
        for (int s = 0; s < STAGES; s++)
            mbar_init(mbar_base + s * 8, 1);
        asm volatile("fence.proxy.async.shared::cta;" ::: "memory");
    }
    __syncthreads();

    // this block's tile list: tile j -> node = bid + (j>>1)*grid, half = j&1
    const int bid  = blockIdx.x;
    const int grid = gridDim.x;
    const int my_nodes = (n_nodes > bid) ? ((n_nodes - 1 - bid) / grid + 1) : 0;
    const int total = 2 * my_nodes;

    const char* xb = (const char*)x;
    uint32_t smem_base = smem_u32(stage);

    // prologue: fill the ring
    if (tid == 0) {
        for (int j = 0; j < STAGES && j < total; j++) {
            int node = bid + (j >> 1) * grid;
            const char* src = xb + (size_t)node * (NODE_FLOATS * 4)
                                 + (size_t)(j & 1) * HALF_BYTES;
            bulk_load(smem_base + (uint32_t)(j % STAGES) * TILE_BYTES, src, TILE_BYTES,
                      mbar_base + (uint32_t)(j % STAGES) * 8);
        }
    }

    const int m4 = tid & 31;          // 0..31
    const int a  = tid >> 5;          // 0..19
    const int g  = (a >= 10) ? 3 : (a >= 4) ? 2 : (a >= 1) ? 1 : 0;
    const float* __restrict__ wg = w + g * RAD * RAD;
    const int cell = a * 32 + m4;     // offset within an r-slice (float4)

    float4 acc[RAD];

    for (int j = 0; j < total; j++) {
        const int slot = j % STAGES;
        const uint32_t parity = (uint32_t)(j / STAGES) & 1u;
        mbar_wait(mbar_base + (uint32_t)slot * 8, parity);

        const float4* __restrict__ sp = stage + slot * TILE_F4 + cell;
        const int rbase = (j & 1) * HALF_R;

        if ((j & 1) == 0) {
#pragma unroll
            for (int s = 0; s < RAD; s++)
                acc[s] = make_float4(0.f, 0.f, 0.f, 0.f);
        }

#pragma unroll
        for (int r = 0; r < HALF_R; r++) {
            float4 xv = sp[r * (ANG * 32)];
#pragma unroll
            for (int s = 0; s < RAD; s++) {
                float wv = wg[(rbase + r) * RAD + s];
                acc[s].x = fmaf(xv.x, wv, acc[s].x);
                acc[s].y = fmaf(xv.y, wv, acc[s].y);
                acc[s].z = fmaf(xv.z, wv, acc[s].z);
                acc[s].w = fmaf(xv.w, wv, acc[s].w);
            }
        }

        __syncthreads();   // slot consumed by all threads -> safe to refill

        if (tid == 0 && j + STAGES < total) {
            int jj = j + STAGES;
            int node = bid + (jj >> 1) * grid;
            const char* src = xb + (size_t)node * (NODE_FLOATS * 4)
                                 + (size_t)(jj & 1) * HALF_BYTES;
            bulk_load(smem_base + (uint32_t)(jj % STAGES) * TILE_BYTES, src, TILE_BYTES,
                      mbar_base + (uint32_t)(jj % STAGES) * 8);
        }

        if (j & 1) {
            // node finished: store 12 s-slices (512B contiguous per warp)
            int node = bid + (j >> 1) * grid;
            float4* __restrict__ op = out + node * (RAD * ANG * 32) + cell;
#pragma unroll
            for (int s = 0; s < RAD; s++)
                op[s * (ANG * 32)] = acc[s];
        }
    }
}

extern "C" void kernel_launch(void* const* d_in, const int* in_sizes, int n_in,
                              void* d_out, int out_size)
{
    const float* x = (const float*)d_in[0];
    const float* W = (const float*)d_in[1];
    float4* out = (float4*)d_out;

    int n_nodes = in_sizes[0] / NODE_FLOATS;

    // No statics / no caching (harness rule): query + set attributes every
    // call. Both APIs are non-stream-ordered and graph-capture-safe.
    int sm_count = 0, dev = 0;
    if (cudaGetDevice(&dev) != cudaSuccess ||
        cudaDeviceGetAttribute(&sm_count, cudaDevAttrMultiProcessorCount, dev) != cudaSuccess ||
        sm_count <= 0) {
        sm_count = 148;   // sm_100a B200 fallback
    }
    cudaFuncSetAttribute(srlt_kernel,
                         cudaFuncAttributeMaxDynamicSharedMemorySize,
                         STAGES * TILE_BYTES);

    int grid = sm_count < n_nodes ? sm_count : n_nodes;
    if (grid < 1) grid = 1;
    srlt_kernel<<<grid, THREADS, STAGES * TILE_BYTES>>>(x, W, out, n_nodes);
}